// round 11
// baseline (speedup 1.0000x reference)
#include <cuda_runtime.h>
#include <math.h>
#include <stdint.h>

#define T_DATA 100000
#define K_DIM  1000
#define SUB    20
#define TSYN   201

// ---------------- device scratch (no allocs allowed) ----------------
__device__ float g_syn[2][SUB][T_DATA];   // GEMM output  [e/i][s][t]
__device__ float g_sin[2][SUB][T_DATA];   // conv output  [e/i][s][t]

// ============================ helpers ========================================
__device__ __forceinline__ uint32_t smem_u32(const void* p){
    uint32_t a;
    asm("{ .reg .u64 t; cvta.to.shared.u64 t, %1; cvt.u32.u64 %0, t; }" : "=r"(a) : "l"(p));
    return a;
}
__device__ __forceinline__ uint32_t tf32c(float x){
    uint32_t r; asm("cvt.rna.tf32.f32 %0, %1;" : "=r"(r) : "f"(x)); return r;
}
__device__ __forceinline__ void mma_t(float4& d,
    uint32_t a0, uint32_t a1, uint32_t a2, uint32_t a3, uint32_t b0, uint32_t b1){
    asm("mma.sync.aligned.m16n8k8.row.col.f32.tf32.tf32.f32 "
        "{%0,%1,%2,%3},{%4,%5,%6,%7},{%8,%9},{%0,%1,%2,%3};"
        : "+f"(d.x), "+f"(d.y), "+f"(d.z), "+f"(d.w)
        : "r"(a0), "r"(a1), "r"(a2), "r"(a3), "r"(b0), "r"(b1));
}
__device__ __forceinline__ void cpa16(uint32_t dst, const float* src, uint32_t szb){
    asm volatile("cp.async.cg.shared.global [%0], [%1], 16, %2;"
                 :: "r"(dst), "l"(src), "r"(szb) : "memory");
}
#define CP_COMMIT() asm volatile("cp.async.commit_group;" ::: "memory")
#define CP_WAIT(n)  asm volatile("cp.async.wait_group %0;" :: "n"(n) : "memory")

// ============================ GEMM (mma.sync tf32, cp.async pipeline) ========
// 256 threads / 8 warps, each warp owns a 16-row m-tile. Per CTA rows
// [row0, row0+128). For mat in {e,i}: D[128,24] = A[128,K]*B[24,K]^T
// (B rows 20..23 zero-filled). Pitch 20 floats -> conflict-free frags.
#define PCH    20
#define A_OFS  2560                // 128*20 floats per A mat
#define B_OFS  480                 // 24*20 floats per B mat
#define STGF   6080                // floats/stage: 2*2560 + 2*480 (24320 B)
#define NSTG   3
#define NCHK   63                  // 63 chunks * 16 k = 1008 >= K (zero-fill)

__global__ __launch_bounds__(256, 3) void mma_gemm(
    const float* __restrict__ Se, const float* __restrict__ Si,
    const float* __restrict__ Ce, const float* __restrict__ Ci)
{
    extern __shared__ float smf[];
    const uint32_t smb = smem_u32(smf);
    const int tid = threadIdx.x, wid = tid >> 5, lane = tid & 31;
    const int group = lane >> 2, tig = lane & 3;
    const int row0 = blockIdx.x * 128;

    // ---- cp.async staging geometry ----
    // A: slot idx = i*256 + tid, i<4 : mt = i>>1, row = (tid>>2) + (i&1)*64, c4 = tid&3
    const int ac4 = tid & 3;
    const int arow = tid >> 2;                 // 0..63
    const float* aG[4]; uint32_t aS[4];
    #pragma unroll
    for (int i = 0; i < 4; i++){
        int mt  = i >> 1;
        int row = arow + (i & 1) * 64;
        int gr  = row0 + row; if (gr >= T_DATA) gr = T_DATA - 1;   // clamp (stores guarded)
        aG[i] = (mt ? Si : Se) + (size_t)gr * K_DIM + ac4 * 4;
        aS[i] = (uint32_t)(mt * A_OFS + row * PCH + ac4 * 4) * 4u;
    }
    // B: one slot for tid < 192 : mt = tid/96, r = tid%96, n = r>>2, c4 = r&3
    const bool bslot = (tid < 192);
    const int bid2 = bslot ? tid : 0;
    const int bmt = bid2 / 96, br = bid2 % 96;
    const int bn = br >> 2, bc4 = br & 3;
    const bool bval = bslot && (bn < SUB);
    const float* bG = (bmt ? Ci : Ce) + (size_t)((bn < SUB) ? bn : 0) * K_DIM + bc4 * 4;
    const uint32_t bS = (uint32_t)(2 * A_OFS + bmt * B_OFS + bn * PCH + bc4 * 4) * 4u;

    float4 acc[2][3];
    #pragma unroll
    for (int mt = 0; mt < 2; mt++)
        #pragma unroll
        for (int nt = 0; nt < 3; nt++)
            acc[mt][nt] = make_float4(0.f, 0.f, 0.f, 0.f);

    // ---- issue one chunk's cp.async group ----
    auto issue = [&](int c){
        const uint32_t sbase = smb + (uint32_t)(c % NSTG) * (STGF * 4u);
        const int k0 = c * 16;
        const uint32_t szA = (k0 + ac4 * 4 < K_DIM) ? 16u : 0u;
        #pragma unroll
        for (int i = 0; i < 4; i++)
            cpa16(sbase + aS[i], aG[i] + k0, szA);
        if (bslot){
            uint32_t sz = (bval && (k0 + bc4 * 4 < K_DIM)) ? 16u : 0u;
            cpa16(sbase + bS, bG + k0, sz);
        }
        CP_COMMIT();
    };

    issue(0);
    issue(1);

    const int cbaseA = wid * 16 * PCH + group * PCH + tig;
    const int cbaseB = 2 * A_OFS + group * PCH + tig;

    for (int c = 0; c < NCHK; c++){
        if (c < NCHK - 1) { CP_WAIT(1); } else { CP_WAIT(0); }
        __syncthreads();
        if (c + 2 < NCHK) issue(c + 2);

        const float* base = smf + (c % NSTG) * STGF;
        #pragma unroll
        for (int ks = 0; ks < 2; ks++){
            const int kb = ks * 8;
            uint32_t A[2][4];
            #pragma unroll
            for (int mt = 0; mt < 2; mt++){
                const float* ab = base + mt * A_OFS + cbaseA + kb;
                A[mt][0] = tf32c(ab[0]);
                A[mt][1] = tf32c(ab[8 * PCH]);
                A[mt][2] = tf32c(ab[4]);
                A[mt][3] = tf32c(ab[8 * PCH + 4]);
            }
            uint32_t B0[2][3], B1[2][3];
            #pragma unroll
            for (int mt = 0; mt < 2; mt++)
                #pragma unroll
                for (int nt = 0; nt < 3; nt++){
                    const float* bbp = base + mt * B_OFS + cbaseB + nt * 8 * PCH + kb;
                    B0[mt][nt] = tf32c(bbp[0]);
                    B1[mt][nt] = tf32c(bbp[4]);
                }
            #pragma unroll
            for (int mt = 0; mt < 2; mt++)
                #pragma unroll
                for (int nt = 0; nt < 3; nt++)
                    mma_t(acc[mt][nt],
                          A[mt][0], A[mt][1], A[mt][2], A[mt][3],
                          B0[mt][nt], B1[mt][nt]);
        }
    }

    // ---- epilogue: D frag -> g_syn[mt][n][t] ----
    #pragma unroll
    for (int mt = 0; mt < 2; mt++)
        #pragma unroll
        for (int nt = 0; nt < 3; nt++){
            float4 d = acc[mt][nt];
            int t0 = row0 + wid * 16 + group;
            int n0 = nt * 8 + tig * 2;
            if (n0 < SUB){
                if (t0 < T_DATA){
                    g_syn[mt][n0][t0]     = d.x;
                    g_syn[mt][n0 + 1][t0] = d.y;
                }
                if (t0 + 8 < T_DATA){
                    g_syn[mt][n0][t0 + 8]     = d.z;
                    g_syn[mt][n0 + 1][t0 + 8] = d.w;
                }
            }
        }
}

// ============================ depthwise conv =================================
// out[t] = sum_{k=0..200} w[k] * x[t-200+k]  (front zero-pad; straight correlation)
#define TT 2048

__global__ __launch_bounds__(256) void conv_kernel(
    const float* __restrict__ w_e, const float* __restrict__ w_i)
{
    __shared__ __align__(16) float xs[TT + 232];
    __shared__ __align__(16) float ws[204];

    const int tid = threadIdx.x;
    const long tile0 = (long)blockIdx.x * TT;
    const int id = blockIdx.y;                 // 0..39
    const int mt = id / SUB, s = id % SUB;
    const float* xg = g_syn[mt][s];

    // xs[j] = x(tile0 - 208 + j)    (208 keeps 16-B global alignment)
    for (int idx = tid; idx < (TT + 232)/4; idx += 256){
        long gt = tile0 - 208 + (long)idx*4;
        float4 v;
        if (gt >= 0 && gt + 3 < T_DATA){
            v = *(const float4*)&xg[gt];
        } else {
            float tmp[4];
            #pragma unroll
            for (int k2 = 0; k2 < 4; k2++){
                long g2 = gt + k2;
                tmp[k2] = (g2 >= 0 && g2 < T_DATA) ? xg[g2] : 0.f;
            }
            v = make_float4(tmp[0], tmp[1], tmp[2], tmp[3]);
        }
        *(float4*)&xs[idx*4] = v;
    }
    const float* w = mt ? w_i : w_e;
    for (int idx = tid; idx < 204; idx += 256)
        ws[idx] = (idx < TSYN) ? w[s*TSYN + idx] : 0.f;
    __syncthreads();

    const int tl0 = tid * 8;
    const int x0  = tl0 + 8;                 // xs index of tap k=0 for output tl0
    float a[8];
    #pragma unroll
    for (int j = 0; j < 8; j++) a[j] = 0.f;

    float r[12];
    #pragma unroll
    for (int j = 0; j < 12; j += 4)
        *(float4*)&r[j] = *(const float4*)&xs[x0 + j];

    #pragma unroll
    for (int kb = 0; kb < 204; kb += 4){
        float4 w4 = *(const float4*)&ws[kb];
        #pragma unroll
        for (int j = 0; j < 8; j++)
            a[j] += w4.x*r[j] + w4.y*r[j+1] + w4.z*r[j+2] + w4.w*r[j+3];
        if (kb < 200){
            #pragma unroll
            for (int j = 0; j < 8; j++) r[j] = r[j+4];
            *(float4*)&r[8] = *(const float4*)&xs[x0 + kb + 12];
        }
    }

    long tb = tile0 + tl0;
    if (tb + 7 < T_DATA){
        *(float4*)&g_sin[mt][s][tb]     = make_float4(a[0], a[1], a[2], a[3]);
        *(float4*)&g_sin[mt][s][tb + 4] = make_float4(a[4], a[5], a[6], a[7]);
    } else {
        #pragma unroll
        for (int j = 0; j < 8; j++)
            if (tb + j < T_DATA) g_sin[mt][s][tb + j] = a[j];
    }
}

// ============================ dendritic mix + outputs ========================
__global__ __launch_bounds__(256) void mix_kernel(
    const float* __restrict__ C_den, const float* __restrict__ b_e,
    const float* __restrict__ b_i,   const float* __restrict__ Wsub,
    float* __restrict__ out)
{
    __shared__ float si[SUB][260];
    __shared__ float M[SUB][SUB];
    __shared__ float ew0s;

    const int tid = threadIdx.x;
    const long tile0 = (long)blockIdx.x * 256;

    for (int idx = tid; idx < SUB*SUB; idx += 256){
        int sp = idx % SUB;
        M[idx / SUB][sp] = C_den[idx] * expf(Wsub[sp]);
    }
    if (tid == 0) ew0s = expf(Wsub[0]);

    const long t = tile0 + tid;
    #pragma unroll
    for (int sx = 0; sx < SUB; sx++){
        float v = 0.f;
        if (t < T_DATA)
            v = g_sin[0][sx][t] + g_sin[1][sx][t] + b_e[sx] + b_i[sx];
        si[sx][tid] = v;
    }
    __syncthreads();

    float* outV  = out;
    float* outY1 = out + T_DATA;
    float* outY2 = outY1 + (size_t)T_DATA * SUB;
    const float ew0 = ew0s;

    for (int i = 0; i < 20; i++){
        int idx = i*256 + tid;               // < 5120
        int tl = idx / SUB, sx = idx % SUB;
        long tt = tile0 + tl;
        if (tt < T_DATA){
            float y = si[sx][tl];
            #pragma unroll
            for (int sp = 0; sp < SUB; sp++)
                y += si[sp][tl] * M[sx][sp];
            outY1[tt*SUB + sx] = y;
            outY2[tt*SUB + sx] = y;
            if (sx == 0) outV[tt] = y * ew0;
        }
    }
}

// ================================ launch =====================================
extern "C" void kernel_launch(void* const* d_in, const int* in_sizes, int n_in,
                              void* d_out, int out_size)
{
    const float* S_e   = (const float*)d_in[0];
    const float* S_i   = (const float*)d_in[1];
    const float* C_e   = (const float*)d_in[2];
    const float* C_i   = (const float*)d_in[3];
    const float* C_den = (const float*)d_in[4];
    const float* w_e   = (const float*)d_in[5];
    const float* b_e   = (const float*)d_in[6];
    const float* w_i   = (const float*)d_in[7];
    const float* b_i   = (const float*)d_in[8];
    const float* Wsub  = (const float*)d_in[9];
    float* out = (float*)d_out;

    const int gemm_smem = NSTG * STGF * sizeof(float);   // 72,960 B -> 3 CTAs/SM
    cudaFuncSetAttribute(mma_gemm, cudaFuncAttributeMaxDynamicSharedMemorySize, gemm_smem);

    const int grid = (T_DATA + 127) / 128;               // 782
    mma_gemm<<<grid, 256, gemm_smem>>>(S_e, S_i, C_e, C_i);
    conv_kernel<<<dim3((T_DATA + TT - 1)/TT, 40), 256>>>(w_e, w_i);
    mix_kernel<<<(T_DATA + 255)/256, 256>>>(C_den, b_e, b_i, Wsub, out);
}